// round 9
// baseline (speedup 1.0000x reference)
#include <cuda_runtime.h>
#include <cuda_bf16.h>
#include <math.h>
#include <stdint.h>

#define BB 16
#define CIN 128
#define COUT 128
#define HH 64
#define WW 64
#define ATT 16
#define KN 4
#define BN_EPS 1e-5f

// ---------------------------------------------------------------------------
// scratch (device globals; no allocation allowed)
// ---------------------------------------------------------------------------
__device__ float g_pooled[BB * CIN];
__device__ float g_coef[BB * KN * 9];
__device__ float g_ch[BB * CIN];
__device__ float g_fl[BB * COUT];
__device__ float g_spa[BB * 9];
// agg filters pre-split to bf16: layout [b][tap][o(128)][i(128)]
__device__ __align__(128) __nv_bfloat16 g_ah[(size_t)BB * 9 * 128 * 128];
__device__ __align__(128) __nv_bfloat16 g_al[(size_t)BB * 9 * 128 * 128];

// ---------------------------------------------------------------------------
// asm helpers
// ---------------------------------------------------------------------------
__device__ __forceinline__ uint32_t smem_u32(const void* p) {
    uint32_t a;
    asm("{ .reg .u64 t; cvta.to.shared.u64 t, %1; cvt.u32.u64 %0, t; }" : "=r"(a) : "l"(p));
    return a;
}
__device__ __forceinline__ void ldsm_x4(uint32_t* r, uint32_t a) {
    asm volatile("ldmatrix.sync.aligned.m8n8.x4.shared.b16 {%0,%1,%2,%3}, [%4];"
                 : "=r"(r[0]), "=r"(r[1]), "=r"(r[2]), "=r"(r[3]) : "r"(a));
}
__device__ __forceinline__ void ldsm_x2(uint32_t* r, uint32_t a) {
    asm volatile("ldmatrix.sync.aligned.m8n8.x2.shared.b16 {%0,%1}, [%2];"
                 : "=r"(r[0]), "=r"(r[1]) : "r"(a));
}
__device__ __forceinline__ void mma16816(float* c, const uint32_t* a, const uint32_t* b) {
    asm volatile(
        "mma.sync.aligned.m16n8k16.row.col.f32.bf16.bf16.f32 "
        "{%0,%1,%2,%3}, {%4,%5,%6,%7}, {%8,%9}, {%0,%1,%2,%3};"
        : "+f"(c[0]), "+f"(c[1]), "+f"(c[2]), "+f"(c[3])
        : "r"(a[0]), "r"(a[1]), "r"(a[2]), "r"(a[3]), "r"(b[0]), "r"(b[1]));
}

// ---------------- kernel 1: global average pool ----------------------------
__global__ void pool_kernel(const float* __restrict__ x) {
    int bi = blockIdx.x;
    const float4* xp = (const float4*)(x + (size_t)bi * HH * WW);
    float s = 0.f;
    for (int t = threadIdx.x; t < HH * WW / 4; t += 256) {
        float4 v = xp[t];
        s += v.x + v.y + v.z + v.w;
    }
#pragma unroll
    for (int o = 16; o; o >>= 1) s += __shfl_down_sync(0xffffffff, s, o);
    __shared__ float ws[8];
    if ((threadIdx.x & 31) == 0) ws[threadIdx.x >> 5] = s;
    __syncthreads();
    if (threadIdx.x == 0) {
        float t = 0.f;
#pragma unroll
        for (int k = 0; k < 8; k++) t += ws[k];
        g_pooled[bi] = t * (1.0f / (HH * WW));
    }
}

// ---------------- kernel 2: attention trunk + branches (1 block) -----------
__global__ void attn_kernel(
    const float* __restrict__ fc_w,
    const float* __restrict__ bn_gamma, const float* __restrict__ bn_beta,
    const float* __restrict__ bn_mean, const float* __restrict__ bn_var,
    const float* __restrict__ ch_w, const float* __restrict__ ch_b,
    const float* __restrict__ flt_w, const float* __restrict__ flt_b,
    const float* __restrict__ spa_w, const float* __restrict__ spa_b,
    const float* __restrict__ fld_w, const float* __restrict__ fld_b,
    const float* __restrict__ ker_w, const float* __restrict__ ker_b) {
    __shared__ float sp[BB][CIN];
    __shared__ float sh[BB][ATT];
    __shared__ float sfld[BB][9];
    __shared__ float sker[BB][KN];
    int tid = threadIdx.x;
    for (int t = tid; t < BB * CIN; t += 256) sp[t / CIN][t % CIN] = g_pooled[t];
    __syncthreads();
    {
        int b = tid / ATT, a = tid % ATT;
        float s = 0.f;
#pragma unroll 16
        for (int i = 0; i < CIN; i++) s += sp[b][i] * fc_w[a * CIN + i];
        float inv = rsqrtf(bn_var[a] + BN_EPS);
        s = (s - bn_mean[a]) * (bn_gamma[a] * inv) + bn_beta[a];
        sh[b][a] = fmaxf(s, 0.f);
    }
    __syncthreads();
    for (int t = tid; t < BB * CIN; t += 256) {
        int b = t / CIN, i = t % CIN;
        float s = ch_b[i];
#pragma unroll
        for (int a = 0; a < ATT; a++) s += sh[b][a] * ch_w[i * ATT + a];
        g_ch[t] = 1.f / (1.f + expf(-s));
    }
    for (int t = tid; t < BB * COUT; t += 256) {
        int b = t / COUT, o = t % COUT;
        float s = flt_b[o];
#pragma unroll
        for (int a = 0; a < ATT; a++) s += sh[b][a] * flt_w[o * ATT + a];
        g_fl[t] = 1.f / (1.f + expf(-s));
    }
    for (int t = tid; t < BB * 9; t += 256) {
        int b = t / 9, j = t % 9;
        float s = spa_b[j];
#pragma unroll
        for (int a = 0; a < ATT; a++) s += sh[b][a] * spa_w[j * ATT + a];
        g_spa[t] = 1.f / (1.f + expf(-s));
        float s2 = fld_b[j];
#pragma unroll
        for (int a = 0; a < ATT; a++) s2 += sh[b][a] * fld_w[j * ATT + a];
        sfld[b][j] = 1.f / (1.f + expf(-s2));
    }
    if (tid < BB * KN) {
        int b = tid / KN, n = tid % KN;
        float s = ker_b[n];
#pragma unroll
        for (int a = 0; a < ATT; a++) s += sh[b][a] * ker_w[n * ATT + a];
        sker[b][n] = s;
    }
    __syncthreads();
    if (tid < BB) {
        int b = tid;
        float m = -1e30f;
#pragma unroll
        for (int n = 0; n < KN; n++) m = fmaxf(m, sker[b][n]);
        float e[KN], sum = 0.f;
#pragma unroll
        for (int n = 0; n < KN; n++) { e[n] = expf(sker[b][n] - m); sum += e[n]; }
#pragma unroll
        for (int n = 0; n < KN; n++) sker[b][n] = e[n] / sum;
    }
    __syncthreads();
    for (int t = tid; t < BB * KN * 9; t += 256) {
        int b = t / (KN * 9), n = (t / 9) % KN, j = t % 9;
        g_coef[t] = sker[b][n] * sfld[b][j];
    }
}

// ---------------- kernel 3: aggregation -> bf16 hi/lo filter tiles ---------
// (R8 verbatim) grid (64, 9): blockIdx.y owns ONE pq.
__global__ void __launch_bounds__(256) agg_kernel(const float* __restrict__ weight) {
    __shared__ float scoef[BB * KN * 9];
    __shared__ float sch[BB * CIN];
    __shared__ float sfl[BB * COUT];
    __shared__ float sspa[BB * 9];
    for (int t = threadIdx.x; t < BB * KN * 9; t += 256) scoef[t] = g_coef[t];
    for (int t = threadIdx.x; t < BB * CIN; t += 256) sch[t] = g_ch[t];
    for (int t = threadIdx.x; t < BB * COUT; t += 256) sfl[t] = g_fl[t];
    for (int t = threadIdx.x; t < BB * 9; t += 256) sspa[t] = g_spa[t];
    __syncthreads();
    const int oi = blockIdx.x * 256 + threadIdx.x;   // 0..16383
    const int o = oi >> 7, i = oi & 127;
    const int pq = blockIdx.y;
    const size_t nstride = (size_t)COUT * CIN * 81;
    const float* wbase = weight + (size_t)oi * 81 + pq * 9;
    float w[KN * 9];
#pragma unroll
    for (int n = 0; n < KN; n++)
#pragma unroll
        for (int uv = 0; uv < 9; uv++)
            w[n * 9 + uv] = __ldg(wbase + n * nstride + uv);
#pragma unroll 1
    for (int bg = 0; bg < 4; bg++) {
        const int b0 = bg * 4;
        float acc[4] = {0.f, 0.f, 0.f, 0.f};
#pragma unroll
        for (int k = 0; k < KN * 9; k++) {
            float wv = w[k];
#pragma unroll
            for (int bb = 0; bb < 4; bb++)
                acc[bb] += wv * scoef[(b0 + bb) * (KN * 9) + k];
        }
#pragma unroll
        for (int bb = 0; bb < 4; bb++) {
            int b = b0 + bb;
            float s = acc[bb] * sch[b * CIN + i] * sfl[b * COUT + o] * sspa[b * 9 + pq];
            __nv_bfloat16 h = __float2bfloat16(s);
            __nv_bfloat16 l = __float2bfloat16(s - __bfloat162float(h));
            size_t oidx = (((size_t)b * 9 + pq) * 128 + o) * 128 + i;
            g_ah[oidx] = h;
            g_al[oidx] = l;
        }
    }
}

// ---------------- kernel 4: implicit-GEMM conv, shared im2col window -------
// kc outer / tap inner. Per kc: build 4-row x 66-col x 32-i window (bf16
// hi/lo, 144B per pixel slot) ONCE; all 9 taps read shifted B fragments from
// it via per-lane ldmatrix addresses. A-copy per (tap,kc) as in R8.
#define APITCH 80
#define XPIX 144
#define XCOLS 66
#define XROWS 4
#define SM_AH 0
#define SM_AL 10240
#define SM_X  20480
#define SM_TOTAL (SM_X + XROWS * XCOLS * XPIX)   // 58496

__global__ void __launch_bounds__(256, 2) conv_mma_kernel(const float* __restrict__ x,
                                                          float* __restrict__ out) {
    extern __shared__ __align__(16) char sm[];
    const uint32_t sbase = smem_u32(sm);

    const int tid = threadIdx.x;
    const int wid = tid >> 5;
    const int lid = tid & 31;
    const int b = blockIdx.y;
    const int y0 = blockIdx.x * 2;         // two output rows y0, y0+1

    const int mbase = (wid >> 2) * 64;
    const int nbase = (wid & 3) * 32;

    float acc[4][4][4];
#pragma unroll
    for (int mt = 0; mt < 4; mt++)
#pragma unroll
        for (int nt = 0; nt < 4; nt++)
#pragma unroll
            for (int r = 0; r < 4; r++) acc[mt][nt][r] = 0.f;

    const float* xb = x + (size_t)b * CIN * HH * WW;

    // A-copy thread mapping: o = tid >> 1, u = tid & 1
    const int ao = tid >> 1;
    const int au = tid & 1;

    // ldmatrix lane mapping (as R8)
    const int r8 = lid & 7;
    const int g1 = (lid >> 3) & 1;
    const int g2 = lid >> 4;
    const uint32_t aoff = (uint32_t)((mbase + g1 * 8 + r8) * APITCH + g2 * 16);

    // per-lane B base addresses into the x-window (tap/pass/ks-independent)
    uint32_t bb[4];
#pragma unroll
    for (int nt = 0; nt < 4; nt++) {
        int n = nbase + nt * 8 + r8;
        int rp = n >> 6, px = n & 63;
        bb[nt] = sbase + SM_X + (uint32_t)(((rp + 1) * XCOLS + (px + 1)) * XPIX) +
                 (uint32_t)(g1 * 16);
    }

    for (int kc = 0; kc < 4; kc++) {
        const int ic0 = kc * 32;
        // ---- build x window: 4 rows x 66 cols x 32 i, hi/lo split ----
        for (int s = tid; s < XROWS * XCOLS; s += 256) {
            const int row = s / XCOLS, c = s % XCOLS;
            const int gy = y0 - 1 + row, gx = c - 1;
            const bool ok = (gy >= 0) && (gy < HH) && (gx >= 0) && (gx < WW);
            const float* src = xb + ((size_t)ic0 * HH + gy) * WW + gx;
            __nv_bfloat16 hi[32], lo[32];
#pragma unroll
            for (int kk = 0; kk < 32; kk++) {
                float v = ok ? __ldg(src + (size_t)kk * (HH * WW)) : 0.f;
                __nv_bfloat16 h = __float2bfloat16(v);
                hi[kk] = h;
                lo[kk] = __float2bfloat16(v - __bfloat162float(h));
            }
            char* d = sm + SM_X + s * XPIX;
#pragma unroll
            for (int j = 0; j < 4; j++) {
                *(uint4*)(d + j * 16) = ((const uint4*)hi)[j];
                *(uint4*)(d + 64 + j * 16) = ((const uint4*)lo)[j];
            }
        }
        __syncthreads();

        for (int tap = 0; tap < 9; tap++) {
            // ---- A copy: 128 o x 32 k bf16 hi/lo (R8 pattern) ----
            {
                const size_t abase = (((size_t)b * 9 + tap) * 128 + ao) * 128 + ic0;
                const uint4* rh = (const uint4*)(g_ah + abase);
                const uint4* rl = (const uint4*)(g_al + abase);
                uint4 h0 = rh[au * 2], h1 = rh[au * 2 + 1];
                uint4 l0 = rl[au * 2], l1 = rl[au * 2 + 1];
                char* dh = sm + SM_AH + ao * APITCH + au * 32;
                char* dl = sm + SM_AL + ao * APITCH + au * 32;
                *(uint4*)(dh) = h0;  *(uint4*)(dh + 16) = h1;
                *(uint4*)(dl) = l0;  *(uint4*)(dl + 16) = l1;
            }
            __syncthreads();

            const int p = tap / 3 - 1, q = tap % 3 - 1;
            const int bdel = (p * XCOLS + q) * XPIX;

            // ---- MMA: 3 passes x 2 k16, ldmatrix from shared window ----
#pragma unroll
            for (int pass = 0; pass < 3; pass++) {
                const uint32_t Asm = sbase + (pass == 1 ? (uint32_t)SM_AL : (uint32_t)SM_AH);
                const int bsel = (pass == 2) ? 64 : 0;     // lo plane within pixel slot
#pragma unroll
                for (int ks = 0; ks < 2; ks++) {
                    const int koff = bdel + bsel + ks * 32;
                    uint32_t bfr[4][2];
#pragma unroll
                    for (int nt = 0; nt < 4; nt++)
                        ldsm_x2(bfr[nt], bb[nt] + (uint32_t)koff);
                    const uint32_t kb = (uint32_t)(ks * 32);
#pragma unroll
                    for (int mt = 0; mt < 4; mt++) {
                        uint32_t afr[4];
                        ldsm_x4(afr, Asm + aoff + (uint32_t)(mt * 16 * APITCH) + kb);
#pragma unroll
                        for (int nt = 0; nt < 4; nt++)
                            mma16816(acc[mt][nt], afr, bfr[nt]);
                    }
                }
            }
            __syncthreads();
        }
    }

    // ---- epilogue: direct stores (ch/fl/spa folded into agg) ----
    float* ob = out + (size_t)b * COUT * HH * WW;
#pragma unroll
    for (int mt = 0; mt < 4; mt++) {
        const int o = mbase + mt * 16 + (lid >> 2);
#pragma unroll
        for (int nt = 0; nt < 4; nt++) {
            const int nn = nbase + nt * 8 + (lid & 3) * 2;
            const int rp = nn >> 6, px = nn & 63;
            float* dst = ob + ((size_t)o * HH + (y0 + rp)) * WW + px;
            float2 v0 = make_float2(acc[mt][nt][0], acc[mt][nt][1]);
            float2 v1 = make_float2(acc[mt][nt][2], acc[mt][nt][3]);
            *(float2*)(dst) = v0;
            *(float2*)(dst + 8 * (size_t)HH * WW) = v1;
        }
    }
}

// ---------------- launch ----------------------------------------------------
extern "C" void kernel_launch(void* const* d_in, const int* in_sizes, int n_in,
                              void* d_out, int out_size) {
    const float* x        = (const float*)d_in[0];
    const float* weight   = (const float*)d_in[1];
    const float* fc_w     = (const float*)d_in[2];
    const float* bn_gamma = (const float*)d_in[3];
    const float* bn_beta  = (const float*)d_in[4];
    const float* bn_mean  = (const float*)d_in[5];
    const float* bn_var   = (const float*)d_in[6];
    const float* ch_w     = (const float*)d_in[7];
    const float* ch_b     = (const float*)d_in[8];
    const float* flt_w    = (const float*)d_in[9];
    const float* flt_b    = (const float*)d_in[10];
    const float* spa_w    = (const float*)d_in[11];
    const float* spa_b    = (const float*)d_in[12];
    const float* fld_w    = (const float*)d_in[13];
    const float* fld_b    = (const float*)d_in[14];
    const float* ker_w    = (const float*)d_in[15];
    const float* ker_b    = (const float*)d_in[16];
    float* out = (float*)d_out;

    cudaFuncSetAttribute(conv_mma_kernel,
                         cudaFuncAttributeMaxDynamicSharedMemorySize, SM_TOTAL);

    pool_kernel<<<BB * CIN, 256>>>(x);
    attn_kernel<<<1, 256>>>(fc_w, bn_gamma, bn_beta, bn_mean, bn_var,
                            ch_w, ch_b, flt_w, flt_b, spa_w, spa_b,
                            fld_w, fld_b, ker_w, ker_b);
    agg_kernel<<<dim3(64, 9), 256>>>(weight);
    conv_mma_kernel<<<dim3(32, BB), 256, SM_TOTAL>>>(x, out);
}

// round 10
// speedup vs baseline: 1.0157x; 1.0157x over previous
#include <cuda_runtime.h>
#include <cuda_bf16.h>
#include <math.h>
#include <stdint.h>

#define BB 16
#define CIN 128
#define COUT 128
#define HH 64
#define WW 64
#define ATT 16
#define KN 4
#define BN_EPS 1e-5f

// ---------------------------------------------------------------------------
// scratch (device globals; no allocation allowed)
// ---------------------------------------------------------------------------
__device__ float g_pooled[BB * CIN];
__device__ float g_coef[BB * KN * 9];
__device__ float g_ch[BB * CIN];
__device__ float g_fl[BB * COUT];
__device__ float g_spa[BB * 9];
// agg filters pre-split to bf16: layout [b][tap][o(128)][i(128)]
__device__ __align__(128) __nv_bfloat16 g_ah[(size_t)BB * 9 * 128 * 128];
__device__ __align__(128) __nv_bfloat16 g_al[(size_t)BB * 9 * 128 * 128];

// ---------------------------------------------------------------------------
// asm helpers
// ---------------------------------------------------------------------------
__device__ __forceinline__ uint32_t smem_u32(const void* p) {
    uint32_t a;
    asm("{ .reg .u64 t; cvta.to.shared.u64 t, %1; cvt.u32.u64 %0, t; }" : "=r"(a) : "l"(p));
    return a;
}
__device__ __forceinline__ void ldsm_x4(uint32_t* r, uint32_t a) {
    asm volatile("ldmatrix.sync.aligned.m8n8.x4.shared.b16 {%0,%1,%2,%3}, [%4];"
                 : "=r"(r[0]), "=r"(r[1]), "=r"(r[2]), "=r"(r[3]) : "r"(a));
}
__device__ __forceinline__ void ldsm_x2(uint32_t* r, uint32_t a) {
    asm volatile("ldmatrix.sync.aligned.m8n8.x2.shared.b16 {%0,%1}, [%2];"
                 : "=r"(r[0]), "=r"(r[1]) : "r"(a));
}
__device__ __forceinline__ void mma16816(float* c, const uint32_t* a, const uint32_t* b) {
    asm volatile(
        "mma.sync.aligned.m16n8k16.row.col.f32.bf16.bf16.f32 "
        "{%0,%1,%2,%3}, {%4,%5,%6,%7}, {%8,%9}, {%0,%1,%2,%3};"
        : "+f"(c[0]), "+f"(c[1]), "+f"(c[2]), "+f"(c[3])
        : "r"(a[0]), "r"(a[1]), "r"(a[2]), "r"(a[3]), "r"(b[0]), "r"(b[1]));
}

// ---------------- kernel 1: global average pool ----------------------------
__global__ void pool_kernel(const float* __restrict__ x) {
    int bi = blockIdx.x;
    const float4* xp = (const float4*)(x + (size_t)bi * HH * WW);
    float s = 0.f;
    for (int t = threadIdx.x; t < HH * WW / 4; t += 256) {
        float4 v = xp[t];
        s += v.x + v.y + v.z + v.w;
    }
#pragma unroll
    for (int o = 16; o; o >>= 1) s += __shfl_down_sync(0xffffffff, s, o);
    __shared__ float ws[8];
    if ((threadIdx.x & 31) == 0) ws[threadIdx.x >> 5] = s;
    __syncthreads();
    if (threadIdx.x == 0) {
        float t = 0.f;
#pragma unroll
        for (int k = 0; k < 8; k++) t += ws[k];
        g_pooled[bi] = t * (1.0f / (HH * WW));
    }
}

// ---------------- kernel 2: attention trunk + branches (1 block) -----------
__global__ void attn_kernel(
    const float* __restrict__ fc_w,
    const float* __restrict__ bn_gamma, const float* __restrict__ bn_beta,
    const float* __restrict__ bn_mean, const float* __restrict__ bn_var,
    const float* __restrict__ ch_w, const float* __restrict__ ch_b,
    const float* __restrict__ flt_w, const float* __restrict__ flt_b,
    const float* __restrict__ spa_w, const float* __restrict__ spa_b,
    const float* __restrict__ fld_w, const float* __restrict__ fld_b,
    const float* __restrict__ ker_w, const float* __restrict__ ker_b) {
    __shared__ float sp[BB][CIN];
    __shared__ float sh[BB][ATT];
    __shared__ float sfld[BB][9];
    __shared__ float sker[BB][KN];
    int tid = threadIdx.x;
    for (int t = tid; t < BB * CIN; t += 256) sp[t / CIN][t % CIN] = g_pooled[t];
    __syncthreads();
    {
        int b = tid / ATT, a = tid % ATT;
        float s = 0.f;
#pragma unroll 16
        for (int i = 0; i < CIN; i++) s += sp[b][i] * fc_w[a * CIN + i];
        float inv = rsqrtf(bn_var[a] + BN_EPS);
        s = (s - bn_mean[a]) * (bn_gamma[a] * inv) + bn_beta[a];
        sh[b][a] = fmaxf(s, 0.f);
    }
    __syncthreads();
    for (int t = tid; t < BB * CIN; t += 256) {
        int b = t / CIN, i = t % CIN;
        float s = ch_b[i];
#pragma unroll
        for (int a = 0; a < ATT; a++) s += sh[b][a] * ch_w[i * ATT + a];
        g_ch[t] = 1.f / (1.f + expf(-s));
    }
    for (int t = tid; t < BB * COUT; t += 256) {
        int b = t / COUT, o = t % COUT;
        float s = flt_b[o];
#pragma unroll
        for (int a = 0; a < ATT; a++) s += sh[b][a] * flt_w[o * ATT + a];
        g_fl[t] = 1.f / (1.f + expf(-s));
    }
    for (int t = tid; t < BB * 9; t += 256) {
        int b = t / 9, j = t % 9;
        float s = spa_b[j];
#pragma unroll
        for (int a = 0; a < ATT; a++) s += sh[b][a] * spa_w[j * ATT + a];
        g_spa[t] = 1.f / (1.f + expf(-s));
        float s2 = fld_b[j];
#pragma unroll
        for (int a = 0; a < ATT; a++) s2 += sh[b][a] * fld_w[j * ATT + a];
        sfld[b][j] = 1.f / (1.f + expf(-s2));
    }
    if (tid < BB * KN) {
        int b = tid / KN, n = tid % KN;
        float s = ker_b[n];
#pragma unroll
        for (int a = 0; a < ATT; a++) s += sh[b][a] * ker_w[n * ATT + a];
        sker[b][n] = s;
    }
    __syncthreads();
    if (tid < BB) {
        int b = tid;
        float m = -1e30f;
#pragma unroll
        for (int n = 0; n < KN; n++) m = fmaxf(m, sker[b][n]);
        float e[KN], sum = 0.f;
#pragma unroll
        for (int n = 0; n < KN; n++) { e[n] = expf(sker[b][n] - m); sum += e[n]; }
#pragma unroll
        for (int n = 0; n < KN; n++) sker[b][n] = e[n] / sum;
    }
    __syncthreads();
    for (int t = tid; t < BB * KN * 9; t += 256) {
        int b = t / (KN * 9), n = (t / 9) % KN, j = t % 9;
        g_coef[t] = sker[b][n] * sfld[b][j];
    }
}

// ---------------- kernel 3: aggregation -> bf16 hi/lo filter tiles ---------
// (R8 verbatim) grid (64, 9): blockIdx.y owns ONE pq.
__global__ void __launch_bounds__(256) agg_kernel(const float* __restrict__ weight) {
    __shared__ float scoef[BB * KN * 9];
    __shared__ float sch[BB * CIN];
    __shared__ float sfl[BB * COUT];
    __shared__ float sspa[BB * 9];
    for (int t = threadIdx.x; t < BB * KN * 9; t += 256) scoef[t] = g_coef[t];
    for (int t = threadIdx.x; t < BB * CIN; t += 256) sch[t] = g_ch[t];
    for (int t = threadIdx.x; t < BB * COUT; t += 256) sfl[t] = g_fl[t];
    for (int t = threadIdx.x; t < BB * 9; t += 256) sspa[t] = g_spa[t];
    __syncthreads();
    const int oi = blockIdx.x * 256 + threadIdx.x;   // 0..16383
    const int o = oi >> 7, i = oi & 127;
    const int pq = blockIdx.y;
    const size_t nstride = (size_t)COUT * CIN * 81;
    const float* wbase = weight + (size_t)oi * 81 + pq * 9;
    float w[KN * 9];
#pragma unroll
    for (int n = 0; n < KN; n++)
#pragma unroll
        for (int uv = 0; uv < 9; uv++)
            w[n * 9 + uv] = __ldg(wbase + n * nstride + uv);
#pragma unroll 1
    for (int bg = 0; bg < 4; bg++) {
        const int b0 = bg * 4;
        float acc[4] = {0.f, 0.f, 0.f, 0.f};
#pragma unroll
        for (int k = 0; k < KN * 9; k++) {
            float wv = w[k];
#pragma unroll
            for (int bb = 0; bb < 4; bb++)
                acc[bb] += wv * scoef[(b0 + bb) * (KN * 9) + k];
        }
#pragma unroll
        for (int bb = 0; bb < 4; bb++) {
            int b = b0 + bb;
            float s = acc[bb] * sch[b * CIN + i] * sfl[b * COUT + o] * sspa[b * 9 + pq];
            __nv_bfloat16 h = __float2bfloat16(s);
            __nv_bfloat16 l = __float2bfloat16(s - __bfloat162float(h));
            size_t oidx = (((size_t)b * 9 + pq) * 128 + o) * 128 + i;
            g_ah[oidx] = h;
            g_al[oidx] = l;
        }
    }
}

// ---------------- kernel 4: implicit-GEMM conv on mma.sync (bf16 hi/lo) ----
// R8 conv with ONE change: k-chunk 32 -> 64. 18 chunks (9 taps x 2), half the
// __syncthreads, 192 mma per warp per chunk. Dynamic smem 72KB, 2 CTAs/SM.
#define APITCH 144   // 64 k * 2B = 128B payload, padded to 144B (conflict-free)
#define SM_AH 0
#define SM_AL 18432
#define SM_BH 36864
#define SM_BL 55296
#define SM_TOTAL 73728

__global__ void __launch_bounds__(256, 2) conv_mma_kernel(const float* __restrict__ x,
                                                          float* __restrict__ out) {
    extern __shared__ __align__(16) char sm[];
    const uint32_t sbase = smem_u32(sm);

    const int tid = threadIdx.x;
    const int wid = tid >> 5;
    const int lid = tid & 31;
    const int b = blockIdx.y;
    const int y0 = blockIdx.x * 2;         // two output rows y0, y0+1

    const int mbase = (wid >> 2) * 64;
    const int nbase = (wid & 3) * 32;

    float acc[4][4][4];
#pragma unroll
    for (int mt = 0; mt < 4; mt++)
#pragma unroll
        for (int nt = 0; nt < 4; nt++)
#pragma unroll
            for (int r = 0; r < 4; r++) acc[mt][nt][r] = 0.f;

    const float* xb = x + (size_t)b * CIN * HH * WW;

    // B-build thread mapping: bn = pixel, ihalf -> i offset 0/32 within chunk
    const int bn = tid & 127;
    const int ihalf = tid >> 7;
    const int brp = bn >> 6;
    const int bpx = bn & 63;

    // A-copy thread mapping: ao = o row, au picks 64B half of 128B payload
    const int ao = tid >> 1;
    const int au = tid & 1;

    // ldmatrix lane mapping (validated R8)
    const int r8 = lid & 7;
    const int g1 = (lid >> 3) & 1;
    const int g2 = lid >> 4;
    const uint32_t aoff = (uint32_t)((mbase + g1 * 8 + r8) * APITCH + g2 * 16);
    const uint32_t boff = (uint32_t)((nbase + r8) * APITCH + g1 * 16);

    for (int tap = 0; tap < 9; tap++) {
        const int p = tap / 3 - 1;
        const int q = tap % 3 - 1;
        const int gy = y0 + brp + p;
        const int gx = bpx + q;
        const bool inb = (gx >= 0) && (gx < WW) && (gy >= 0) && (gy < HH);
        const float* xpix = xb + ((size_t)gy * WW + gx);
        const size_t abase = (((size_t)b * 9 + tap) * 128 + ao) * 128;

        for (int kc = 0; kc < 2; kc++) {
            const int ic0 = kc * 64;
            // ---- A copy: 128 o x 64 k bf16 hi/lo (4 uint4 per plane) ----
            {
                const uint4* rh = (const uint4*)(g_ah + abase + ic0);
                const uint4* rl = (const uint4*)(g_al + abase + ic0);
                char* dh = sm + SM_AH + ao * APITCH + au * 64;
                char* dl = sm + SM_AL + ao * APITCH + au * 64;
#pragma unroll
                for (int j = 0; j < 4; j++) {
                    uint4 hv = rh[au * 4 + j];
                    uint4 lv = rl[au * 4 + j];
                    *(uint4*)(dh + j * 16) = hv;
                    *(uint4*)(dl + j * 16) = lv;
                }
            }
            // ---- B build: [n=128][k=64], two 16-wide sub-batches ----
            {
#pragma unroll
                for (int sb2 = 0; sb2 < 2; sb2++) {
                    __nv_bfloat16 hi[16], lo[16];
                    const float* src =
                        xpix + (size_t)(ic0 + ihalf * 32 + sb2 * 16) * (HH * WW);
#pragma unroll
                    for (int kk = 0; kk < 16; kk++) {
                        float v = inb ? __ldg(src + (size_t)kk * (HH * WW)) : 0.f;
                        __nv_bfloat16 h = __float2bfloat16(v);
                        hi[kk] = h;
                        lo[kk] = __float2bfloat16(v - __bfloat162float(h));
                    }
                    char* dh = sm + SM_BH + bn * APITCH + ihalf * 64 + sb2 * 32;
                    char* dl = sm + SM_BL + bn * APITCH + ihalf * 64 + sb2 * 32;
                    *(uint4*)(dh) = *(const uint4*)(hi);
                    *(uint4*)(dh + 16) = *(const uint4*)(hi + 8);
                    *(uint4*)(dl) = *(const uint4*)(lo);
                    *(uint4*)(dl + 16) = *(const uint4*)(lo + 8);
                }
            }
            __syncthreads();

            // ---- MMA: 3 passes (AhBh, AlBh, AhBl) x 4 k16, ldmatrix loads ----
#pragma unroll
            for (int pass = 0; pass < 3; pass++) {
                const uint32_t Asm = sbase + (pass == 1 ? (uint32_t)SM_AL : (uint32_t)SM_AH);
                const uint32_t Bsm = sbase + (pass == 2 ? (uint32_t)SM_BL : (uint32_t)SM_BH);
#pragma unroll
                for (int ks = 0; ks < 4; ks++) {
                    const uint32_t kb = (uint32_t)(ks * 32);
                    uint32_t bfr[4][2];
#pragma unroll
                    for (int nt = 0; nt < 4; nt++)
                        ldsm_x2(bfr[nt], Bsm + boff + (uint32_t)(nt * 8 * APITCH) + kb);
#pragma unroll
                    for (int mt = 0; mt < 4; mt++) {
                        uint32_t afr[4];
                        ldsm_x4(afr, Asm + aoff + (uint32_t)(mt * 16 * APITCH) + kb);
#pragma unroll
                        for (int nt = 0; nt < 4; nt++)
                            mma16816(acc[mt][nt], afr, bfr[nt]);
                    }
                }
            }
            __syncthreads();
        }
    }

    // ---- epilogue: direct stores (fl already folded into agg) ----
    float* ob = out + (size_t)b * COUT * HH * WW;
#pragma unroll
    for (int mt = 0; mt < 4; mt++) {
        const int o = mbase + mt * 16 + (lid >> 2);
#pragma unroll
        for (int nt = 0; nt < 4; nt++) {
            const int nn = nbase + nt * 8 + (lid & 3) * 2;
            const int rp = nn >> 6, px = nn & 63;
            float* dst = ob + ((size_t)o * HH + (y0 + rp)) * WW + px;
            float2 v0 = make_float2(acc[mt][nt][0], acc[mt][nt][1]);
            float2 v1 = make_float2(acc[mt][nt][2], acc[mt][nt][3]);
            *(float2*)(dst) = v0;
            *(float2*)(dst + 8 * (size_t)HH * WW) = v1;
        }
    }
}

// ---------------- launch ----------------------------------------------------
extern "C" void kernel_launch(void* const* d_in, const int* in_sizes, int n_in,
                              void* d_out, int out_size) {
    const float* x        = (const float*)d_in[0];
    const float* weight   = (const float*)d_in[1];
    const float* fc_w     = (const float*)d_in[2];
    const float* bn_gamma = (const float*)d_in[3];
    const float* bn_beta  = (const float*)d_in[4];
    const float* bn_mean  = (const float*)d_in[5];
    const float* bn_var   = (const float*)d_in[6];
    const float* ch_w     = (const float*)d_in[7];
    const float* ch_b     = (const float*)d_in[8];
    const float* flt_w    = (const float*)d_in[9];
    const float* flt_b    = (const float*)d_in[10];
    const float* spa_w    = (const float*)d_in[11];
    const float* spa_b    = (const float*)d_in[12];
    const float* fld_w    = (const float*)d_in[13];
    const float* fld_b    = (const float*)d_in[14];
    const float* ker_w    = (const float*)d_in[15];
    const float* ker_b    = (const float*)d_in[16];
    float* out = (float*)d_out;

    cudaFuncSetAttribute(conv_mma_kernel,
                         cudaFuncAttributeMaxDynamicSharedMemorySize, SM_TOTAL);

    pool_kernel<<<BB * CIN, 256>>>(x);
    attn_kernel<<<1, 256>>>(fc_w, bn_gamma, bn_beta, bn_mean, bn_var,
                            ch_w, ch_b, flt_w, flt_b, spa_w, spa_b,
                            fld_w, fld_b, ker_w, ker_b);
    agg_kernel<<<dim3(64, 9), 256>>>(weight);
    conv_mma_kernel<<<dim3(32, BB), 256, SM_TOTAL>>>(x, out);
}

// round 11
// speedup vs baseline: 1.1195x; 1.1022x over previous
#include <cuda_runtime.h>
#include <cuda_bf16.h>
#include <math.h>
#include <stdint.h>

#define BB 16
#define CIN 128
#define COUT 128
#define HH 64
#define WW 64
#define ATT 16
#define KN 4
#define BN_EPS 1e-5f

// ---------------------------------------------------------------------------
// scratch (device globals; no allocation allowed)
// ---------------------------------------------------------------------------
__device__ float g_pooled[BB * CIN];
__device__ float g_coef[BB * KN * 9];
__device__ float g_ch[BB * CIN];
__device__ float g_fl[BB * COUT];
__device__ float g_spa[BB * 9];
// agg filters pre-split to bf16: layout [b][tap][o(128)][i(128)]
__device__ __align__(128) __nv_bfloat16 g_ah[(size_t)BB * 9 * 128 * 128];
__device__ __align__(128) __nv_bfloat16 g_al[(size_t)BB * 9 * 128 * 128];
// x pre-split, NCHW, packed u32 = {bf16 hi <<16 | bf16 lo} per element
__device__ __align__(128) uint32_t g_xs[(size_t)BB * CIN * HH * WW];

// ---------------------------------------------------------------------------
// asm helpers
// ---------------------------------------------------------------------------
__device__ __forceinline__ uint32_t smem_u32(const void* p) {
    uint32_t a;
    asm("{ .reg .u64 t; cvta.to.shared.u64 t, %1; cvt.u32.u64 %0, t; }" : "=r"(a) : "l"(p));
    return a;
}
__device__ __forceinline__ void ldsm_x4(uint32_t* r, uint32_t a) {
    asm volatile("ldmatrix.sync.aligned.m8n8.x4.shared.b16 {%0,%1,%2,%3}, [%4];"
                 : "=r"(r[0]), "=r"(r[1]), "=r"(r[2]), "=r"(r[3]) : "r"(a));
}
__device__ __forceinline__ void ldsm_x2(uint32_t* r, uint32_t a) {
    asm volatile("ldmatrix.sync.aligned.m8n8.x2.shared.b16 {%0,%1}, [%2];"
                 : "=r"(r[0]), "=r"(r[1]) : "r"(a));
}
__device__ __forceinline__ void mma16816(float* c, const uint32_t* a, const uint32_t* b) {
    asm volatile(
        "mma.sync.aligned.m16n8k16.row.col.f32.bf16.bf16.f32 "
        "{%0,%1,%2,%3}, {%4,%5,%6,%7}, {%8,%9}, {%0,%1,%2,%3};"
        : "+f"(c[0]), "+f"(c[1]), "+f"(c[2]), "+f"(c[3])
        : "r"(a[0]), "r"(a[1]), "r"(a[2]), "r"(a[3]), "r"(b[0]), "r"(b[1]));
}
__device__ __forceinline__ uint32_t pack_hilo(float v) {
    __nv_bfloat16 h = __float2bfloat16(v);
    float hf = __bfloat162float(h);
    __nv_bfloat16 l = __float2bfloat16(v - hf);
    return ((uint32_t)__bfloat16_as_ushort(h) << 16) | (uint32_t)__bfloat16_as_ushort(l);
}

// ---------------- kernel 1: fused x hi/lo split + global average pool ------
// One block per (b,i) plane (2048 blocks). Coalesced read+write, pool fused.
__global__ void __launch_bounds__(256) xsplit_pool_kernel(const float* __restrict__ x) {
    const int bi = blockIdx.x;
    const float4* xp = (const float4*)(x + (size_t)bi * HH * WW);
    uint4* xo = (uint4*)(g_xs + (size_t)bi * HH * WW);
    float s = 0.f;
    for (int t = threadIdx.x; t < HH * WW / 4; t += 256) {
        float4 v = xp[t];
        uint4 o;
        o.x = pack_hilo(v.x);
        o.y = pack_hilo(v.y);
        o.z = pack_hilo(v.z);
        o.w = pack_hilo(v.w);
        xo[t] = o;
        s += v.x + v.y + v.z + v.w;
    }
#pragma unroll
    for (int o2 = 16; o2; o2 >>= 1) s += __shfl_down_sync(0xffffffff, s, o2);
    __shared__ float ws[8];
    if ((threadIdx.x & 31) == 0) ws[threadIdx.x >> 5] = s;
    __syncthreads();
    if (threadIdx.x == 0) {
        float t = 0.f;
#pragma unroll
        for (int k = 0; k < 8; k++) t += ws[k];
        g_pooled[bi] = t * (1.0f / (HH * WW));
    }
}

// ---------------- kernel 2: attention trunk + branches (1 block) -----------
__global__ void attn_kernel(
    const float* __restrict__ fc_w,
    const float* __restrict__ bn_gamma, const float* __restrict__ bn_beta,
    const float* __restrict__ bn_mean, const float* __restrict__ bn_var,
    const float* __restrict__ ch_w, const float* __restrict__ ch_b,
    const float* __restrict__ flt_w, const float* __restrict__ flt_b,
    const float* __restrict__ spa_w, const float* __restrict__ spa_b,
    const float* __restrict__ fld_w, const float* __restrict__ fld_b,
    const float* __restrict__ ker_w, const float* __restrict__ ker_b) {
    __shared__ float sp[BB][CIN];
    __shared__ float sh[BB][ATT];
    __shared__ float sfld[BB][9];
    __shared__ float sker[BB][KN];
    int tid = threadIdx.x;
    for (int t = tid; t < BB * CIN; t += 256) sp[t / CIN][t % CIN] = g_pooled[t];
    __syncthreads();
    {
        int b = tid / ATT, a = tid % ATT;
        float s = 0.f;
#pragma unroll 16
        for (int i = 0; i < CIN; i++) s += sp[b][i] * fc_w[a * CIN + i];
        float inv = rsqrtf(bn_var[a] + BN_EPS);
        s = (s - bn_mean[a]) * (bn_gamma[a] * inv) + bn_beta[a];
        sh[b][a] = fmaxf(s, 0.f);
    }
    __syncthreads();
    for (int t = tid; t < BB * CIN; t += 256) {
        int b = t / CIN, i = t % CIN;
        float s = ch_b[i];
#pragma unroll
        for (int a = 0; a < ATT; a++) s += sh[b][a] * ch_w[i * ATT + a];
        g_ch[t] = 1.f / (1.f + expf(-s));
    }
    for (int t = tid; t < BB * COUT; t += 256) {
        int b = t / COUT, o = t % COUT;
        float s = flt_b[o];
#pragma unroll
        for (int a = 0; a < ATT; a++) s += sh[b][a] * flt_w[o * ATT + a];
        g_fl[t] = 1.f / (1.f + expf(-s));
    }
    for (int t = tid; t < BB * 9; t += 256) {
        int b = t / 9, j = t % 9;
        float s = spa_b[j];
#pragma unroll
        for (int a = 0; a < ATT; a++) s += sh[b][a] * spa_w[j * ATT + a];
        g_spa[t] = 1.f / (1.f + expf(-s));
        float s2 = fld_b[j];
#pragma unroll
        for (int a = 0; a < ATT; a++) s2 += sh[b][a] * fld_w[j * ATT + a];
        sfld[b][j] = 1.f / (1.f + expf(-s2));
    }
    if (tid < BB * KN) {
        int b = tid / KN, n = tid % KN;
        float s = ker_b[n];
#pragma unroll
        for (int a = 0; a < ATT; a++) s += sh[b][a] * ker_w[n * ATT + a];
        sker[b][n] = s;
    }
    __syncthreads();
    if (tid < BB) {
        int b = tid;
        float m = -1e30f;
#pragma unroll
        for (int n = 0; n < KN; n++) m = fmaxf(m, sker[b][n]);
        float e[KN], sum = 0.f;
#pragma unroll
        for (int n = 0; n < KN; n++) { e[n] = expf(sker[b][n] - m); sum += e[n]; }
#pragma unroll
        for (int n = 0; n < KN; n++) sker[b][n] = e[n] / sum;
    }
    __syncthreads();
    for (int t = tid; t < BB * KN * 9; t += 256) {
        int b = t / (KN * 9), n = (t / 9) % KN, j = t % 9;
        g_coef[t] = sker[b][n] * sfld[b][j];
    }
}

// ---------------- kernel 3: aggregation -> bf16 hi/lo filter tiles ---------
// (R8 verbatim) grid (64, 9): blockIdx.y owns ONE pq.
__global__ void __launch_bounds__(256) agg_kernel(const float* __restrict__ weight) {
    __shared__ float scoef[BB * KN * 9];
    __shared__ float sch[BB * CIN];
    __shared__ float sfl[BB * COUT];
    __shared__ float sspa[BB * 9];
    for (int t = threadIdx.x; t < BB * KN * 9; t += 256) scoef[t] = g_coef[t];
    for (int t = threadIdx.x; t < BB * CIN; t += 256) sch[t] = g_ch[t];
    for (int t = threadIdx.x; t < BB * COUT; t += 256) sfl[t] = g_fl[t];
    for (int t = threadIdx.x; t < BB * 9; t += 256) sspa[t] = g_spa[t];
    __syncthreads();
    const int oi = blockIdx.x * 256 + threadIdx.x;   // 0..16383
    const int o = oi >> 7, i = oi & 127;
    const int pq = blockIdx.y;
    const size_t nstride = (size_t)COUT * CIN * 81;
    const float* wbase = weight + (size_t)oi * 81 + pq * 9;
    float w[KN * 9];
#pragma unroll
    for (int n = 0; n < KN; n++)
#pragma unroll
        for (int uv = 0; uv < 9; uv++)
            w[n * 9 + uv] = __ldg(wbase + n * nstride + uv);
#pragma unroll 1
    for (int bg = 0; bg < 4; bg++) {
        const int b0 = bg * 4;
        float acc[4] = {0.f, 0.f, 0.f, 0.f};
#pragma unroll
        for (int k = 0; k < KN * 9; k++) {
            float wv = w[k];
#pragma unroll
            for (int bb = 0; bb < 4; bb++)
                acc[bb] += wv * scoef[(b0 + bb) * (KN * 9) + k];
        }
#pragma unroll
        for (int bb = 0; bb < 4; bb++) {
            int b = b0 + bb;
            float s = acc[bb] * sch[b * CIN + i] * sfl[b * COUT + o] * sspa[b * 9 + pq];
            __nv_bfloat16 h = __float2bfloat16(s);
            __nv_bfloat16 l = __float2bfloat16(s - __bfloat162float(h));
            size_t oidx = (((size_t)b * 9 + pq) * 128 + o) * 128 + i;
            g_ah[oidx] = h;
            g_al[oidx] = l;
        }
    }
}

// ---------------- kernel 4: implicit-GEMM conv on mma.sync (bf16 hi/lo) ----
// R8 conv with ONE change: B-build reads pre-split packed u32 x (same
// coalesced NCHW addresses) and splits hi/lo via byte_perm — cvt chain gone.
#define APITCH 80   // 32 k * 2B = 64B payload, padded to 80B (conflict-free)

__global__ void __launch_bounds__(256, 2) conv_mma_kernel(float* __restrict__ out) {
    __shared__ __align__(16) char sm[4 * 128 * APITCH];
    char* smAh = sm;
    char* smAl = sm + 128 * APITCH;
    char* smBh = sm + 2 * 128 * APITCH;
    char* smBl = sm + 3 * 128 * APITCH;
    const uint32_t sbase = smem_u32(sm);

    const int tid = threadIdx.x;
    const int wid = tid >> 5;
    const int lid = tid & 31;
    const int b = blockIdx.y;
    const int y0 = blockIdx.x * 2;         // two output rows y0, y0+1

    const int mbase = (wid >> 2) * 64;
    const int nbase = (wid & 3) * 32;

    float acc[4][4][4];
#pragma unroll
    for (int mt = 0; mt < 4; mt++)
#pragma unroll
        for (int nt = 0; nt < 4; nt++)
#pragma unroll
            for (int r = 0; r < 4; r++) acc[mt][nt][r] = 0.f;

    const uint32_t* xsb = g_xs + (size_t)b * CIN * HH * WW;

    // B-build thread mapping: n = tid & 127 (px index), ihalf = tid >> 7
    const int bn = tid & 127;
    const int ihalf = tid >> 7;            // 0/1 -> i offset 0/16 within chunk
    const int brp = bn >> 6;               // row select
    const int bpx = bn & 63;

    // A-copy thread mapping: o = tid >> 1, u = tid & 1 (2 x uint4 each)
    const int ao = tid >> 1;
    const int au = tid & 1;

    // ldmatrix lane mapping (validated R8)
    const int r8 = lid & 7;
    const int g1 = (lid >> 3) & 1;
    const int g2 = lid >> 4;
    const uint32_t aoff = (uint32_t)((mbase + g1 * 8 + r8) * APITCH + g2 * 16);
    const uint32_t boff = (uint32_t)((nbase + r8) * APITCH + g1 * 16);

    for (int tap = 0; tap < 9; tap++) {
        const int p = tap / 3 - 1;
        const int q = tap % 3 - 1;
        const int gy = y0 + brp + p;
        const int gx = bpx + q;
        const bool inb = (gx >= 0) && (gx < WW) && (gy >= 0) && (gy < HH);
        const uint32_t* xpix = xsb + (inb ? (gy * WW + gx) : 0);
        const size_t abase = (((size_t)b * 9 + tap) * 128 + ao) * 128;

        for (int kc = 0; kc < 4; kc++) {
            const int ic0 = kc * 32;
            // ---- A copy: 128 o x 32 k bf16 hi/lo ----
            {
                const uint4* rh = (const uint4*)(g_ah + abase + ic0);
                const uint4* rl = (const uint4*)(g_al + abase + ic0);
                uint4 h0 = rh[au * 2], h1 = rh[au * 2 + 1];
                uint4 l0 = rl[au * 2], l1 = rl[au * 2 + 1];
                char* dh = smAh + ao * APITCH + au * 32;
                char* dl = smAl + ao * APITCH + au * 32;
                *(uint4*)(dh) = h0;  *(uint4*)(dh + 16) = h1;
                *(uint4*)(dl) = l0;  *(uint4*)(dl + 16) = l1;
            }
            // ---- B build: [n=128][k=32] packed loads + byte_perm split ----
            {
                uint32_t pck[16];
                const uint32_t* src = xpix + (size_t)(ic0 + ihalf * 16) * (HH * WW);
#pragma unroll
                for (int kk = 0; kk < 16; kk++)
                    pck[kk] = inb ? __ldg(src + (size_t)kk * (HH * WW)) : 0u;
                uint32_t h[8], l[8];
#pragma unroll
                for (int j = 0; j < 8; j++) {
                    h[j] = __byte_perm(pck[2 * j], pck[2 * j + 1], 0x7632);
                    l[j] = __byte_perm(pck[2 * j], pck[2 * j + 1], 0x5410);
                }
                char* dh = smBh + bn * APITCH + ihalf * 32;
                char* dl = smBl + bn * APITCH + ihalf * 32;
                *(uint4*)(dh) = *(const uint4*)(h);
                *(uint4*)(dh + 16) = *(const uint4*)(h + 4);
                *(uint4*)(dl) = *(const uint4*)(l);
                *(uint4*)(dl + 16) = *(const uint4*)(l + 4);
            }
            __syncthreads();

            // ---- MMA: 3 passes (AhBh, AlBh, AhBl) x 2 k16, ldmatrix loads ----
#pragma unroll
            for (int pass = 0; pass < 3; pass++) {
                const uint32_t Asm = sbase + (pass == 1 ? 10240u : 0u);
                const uint32_t Bsm = sbase + 20480u + (pass == 2 ? 10240u : 0u);
#pragma unroll
                for (int ks = 0; ks < 2; ks++) {
                    const uint32_t kb = (uint32_t)(ks * 32);
                    uint32_t bfr[4][2];
#pragma unroll
                    for (int nt = 0; nt < 4; nt++)
                        ldsm_x2(bfr[nt], Bsm + boff + (uint32_t)(nt * 8 * APITCH) + kb);
#pragma unroll
                    for (int mt = 0; mt < 4; mt++) {
                        uint32_t afr[4];
                        ldsm_x4(afr, Asm + aoff + (uint32_t)(mt * 16 * APITCH) + kb);
#pragma unroll
                        for (int nt = 0; nt < 4; nt++)
                            mma16816(acc[mt][nt], afr, bfr[nt]);
                    }
                }
            }
            __syncthreads();
        }
    }

    // ---- epilogue: direct stores (fl already folded into agg) ----
    float* ob = out + (size_t)b * COUT * HH * WW;
#pragma unroll
    for (int mt = 0; mt < 4; mt++) {
        const int o = mbase + mt * 16 + (lid >> 2);
#pragma unroll
        for (int nt = 0; nt < 4; nt++) {
            const int nn = nbase + nt * 8 + (lid & 3) * 2;
            const int rp = nn >> 6, px = nn & 63;
            float* dst = ob + ((size_t)o * HH + (y0 + rp)) * WW + px;
            float2 v0 = make_float2(acc[mt][nt][0], acc[mt][nt][1]);
            float2 v1 = make_float2(acc[mt][nt][2], acc[mt][nt][3]);
            *(float2*)(dst) = v0;
            *(float2*)(dst + 8 * (size_t)HH * WW) = v1;
        }
    }
}

// ---------------- launch ----------------------------------------------------
extern "C" void kernel_launch(void* const* d_in, const int* in_sizes, int n_in,
                              void* d_out, int out_size) {
    const float* x        = (const float*)d_in[0];
    const float* weight   = (const float*)d_in[1];
    const float* fc_w     = (const float*)d_in[2];
    const float* bn_gamma = (const float*)d_in[3];
    const float* bn_beta  = (const float*)d_in[4];
    const float* bn_mean  = (const float*)d_in[5];
    const float* bn_var   = (const float*)d_in[6];
    const float* ch_w     = (const float*)d_in[7];
    const float* ch_b     = (const float*)d_in[8];
    const float* flt_w    = (const float*)d_in[9];
    const float* flt_b    = (const float*)d_in[10];
    const float* spa_w    = (const float*)d_in[11];
    const float* spa_b    = (const float*)d_in[12];
    const float* fld_w    = (const float*)d_in[13];
    const float* fld_b    = (const float*)d_in[14];
    const float* ker_w    = (const float*)d_in[15];
    const float* ker_b    = (const float*)d_in[16];
    float* out = (float*)d_out;

    xsplit_pool_kernel<<<BB * CIN, 256>>>(x);
    attn_kernel<<<1, 256>>>(fc_w, bn_gamma, bn_beta, bn_mean, bn_var,
                            ch_w, ch_b, flt_w, flt_b, spa_w, spa_b,
                            fld_w, fld_b, ker_w, ker_b);
    agg_kernel<<<dim3(64, 9), 256>>>(weight);
    conv_mma_kernel<<<dim3(32, BB), 256>>>(out);
}

// round 12
// speedup vs baseline: 1.2401x; 1.1076x over previous
#include <cuda_runtime.h>
#include <cuda_bf16.h>
#include <math.h>
#include <stdint.h>

#define BB 16
#define CIN 128
#define COUT 128
#define HH 64
#define WW 64
#define ATT 16
#define KN 4
#define BN_EPS 1e-5f

// ---------------------------------------------------------------------------
// scratch (device globals; no allocation allowed)
// ---------------------------------------------------------------------------
__device__ float g_pooled[BB * CIN];
__device__ float g_coef[BB * KN * 9];
__device__ float g_ch[BB * CIN];
__device__ float g_fl[BB * COUT];
__device__ float g_spa[BB * 9];
// agg filters pre-split to bf16: layout [b][tap][o(128)][i(128)]
__device__ __align__(128) __nv_bfloat16 g_ah[(size_t)BB * 9 * 128 * 128];
__device__ __align__(128) __nv_bfloat16 g_al[(size_t)BB * 9 * 128 * 128];
// x pre-split, NCHW, packed u32 = {bf16 hi <<16 | bf16 lo} per element
__device__ __align__(128) uint32_t g_xs[(size_t)BB * CIN * HH * WW];

// ---------------------------------------------------------------------------
// asm helpers
// ---------------------------------------------------------------------------
__device__ __forceinline__ uint32_t smem_u32(const void* p) {
    uint32_t a;
    asm("{ .reg .u64 t; cvta.to.shared.u64 t, %1; cvt.u32.u64 %0, t; }" : "=r"(a) : "l"(p));
    return a;
}
__device__ __forceinline__ void cp_async16(uint32_t dst, const void* src) {
    asm volatile("cp.async.cg.shared.global [%0], [%1], 16;"
                 :: "r"(dst), "l"(src) : "memory");
}
__device__ __forceinline__ void ldsm_x4(uint32_t* r, uint32_t a) {
    asm volatile("ldmatrix.sync.aligned.m8n8.x4.shared.b16 {%0,%1,%2,%3}, [%4];"
                 : "=r"(r[0]), "=r"(r[1]), "=r"(r[2]), "=r"(r[3]) : "r"(a));
}
__device__ __forceinline__ void ldsm_x2(uint32_t* r, uint32_t a) {
    asm volatile("ldmatrix.sync.aligned.m8n8.x2.shared.b16 {%0,%1}, [%2];"
                 : "=r"(r[0]), "=r"(r[1]) : "r"(a));
}
__device__ __forceinline__ void mma16816(float* c, const uint32_t* a, const uint32_t* b) {
    asm volatile(
        "mma.sync.aligned.m16n8k16.row.col.f32.bf16.bf16.f32 "
        "{%0,%1,%2,%3}, {%4,%5,%6,%7}, {%8,%9}, {%0,%1,%2,%3};"
        : "+f"(c[0]), "+f"(c[1]), "+f"(c[2]), "+f"(c[3])
        : "r"(a[0]), "r"(a[1]), "r"(a[2]), "r"(a[3]), "r"(b[0]), "r"(b[1]));
}
__device__ __forceinline__ uint32_t pack_hilo(float v) {
    __nv_bfloat16 h = __float2bfloat16(v);
    float hf = __bfloat162float(h);
    __nv_bfloat16 l = __float2bfloat16(v - hf);
    return ((uint32_t)__bfloat16_as_ushort(h) << 16) | (uint32_t)__bfloat16_as_ushort(l);
}

// ---------------- kernel 1: fused x hi/lo split + global average pool ------
__global__ void __launch_bounds__(256) xsplit_pool_kernel(const float* __restrict__ x) {
    const int bi = blockIdx.x;
    const float4* xp = (const float4*)(x + (size_t)bi * HH * WW);
    uint4* xo = (uint4*)(g_xs + (size_t)bi * HH * WW);
    float s = 0.f;
    for (int t = threadIdx.x; t < HH * WW / 4; t += 256) {
        float4 v = xp[t];
        uint4 o;
        o.x = pack_hilo(v.x);
        o.y = pack_hilo(v.y);
        o.z = pack_hilo(v.z);
        o.w = pack_hilo(v.w);
        xo[t] = o;
        s += v.x + v.y + v.z + v.w;
    }
#pragma unroll
    for (int o2 = 16; o2; o2 >>= 1) s += __shfl_down_sync(0xffffffff, s, o2);
    __shared__ float ws[8];
    if ((threadIdx.x & 31) == 0) ws[threadIdx.x >> 5] = s;
    __syncthreads();
    if (threadIdx.x == 0) {
        float t = 0.f;
#pragma unroll
        for (int k = 0; k < 8; k++) t += ws[k];
        g_pooled[bi] = t * (1.0f / (HH * WW));
    }
}

// ---------------- kernel 2: attention trunk + branches (1 block) -----------
__global__ void attn_kernel(
    const float* __restrict__ fc_w,
    const float* __restrict__ bn_gamma, const float* __restrict__ bn_beta,
    const float* __restrict__ bn_mean, const float* __restrict__ bn_var,
    const float* __restrict__ ch_w, const float* __restrict__ ch_b,
    const float* __restrict__ flt_w, const float* __restrict__ flt_b,
    const float* __restrict__ spa_w, const float* __restrict__ spa_b,
    const float* __restrict__ fld_w, const float* __restrict__ fld_b,
    const float* __restrict__ ker_w, const float* __restrict__ ker_b) {
    __shared__ float sp[BB][CIN];
    __shared__ float sh[BB][ATT];
    __shared__ float sfld[BB][9];
    __shared__ float sker[BB][KN];
    int tid = threadIdx.x;
    for (int t = tid; t < BB * CIN; t += 256) sp[t / CIN][t % CIN] = g_pooled[t];
    __syncthreads();
    {
        int b = tid / ATT, a = tid % ATT;
        float s = 0.f;
#pragma unroll 16
        for (int i = 0; i < CIN; i++) s += sp[b][i] * fc_w[a * CIN + i];
        float inv = rsqrtf(bn_var[a] + BN_EPS);
        s = (s - bn_mean[a]) * (bn_gamma[a] * inv) + bn_beta[a];
        sh[b][a] = fmaxf(s, 0.f);
    }
    __syncthreads();
    for (int t = tid; t < BB * CIN; t += 256) {
        int b = t / CIN, i = t % CIN;
        float s = ch_b[i];
#pragma unroll
        for (int a = 0; a < ATT; a++) s += sh[b][a] * ch_w[i * ATT + a];
        g_ch[t] = 1.f / (1.f + expf(-s));
    }
    for (int t = tid; t < BB * COUT; t += 256) {
        int b = t / COUT, o = t % COUT;
        float s = flt_b[o];
#pragma unroll
        for (int a = 0; a < ATT; a++) s += sh[b][a] * flt_w[o * ATT + a];
        g_fl[t] = 1.f / (1.f + expf(-s));
    }
    for (int t = tid; t < BB * 9; t += 256) {
        int b = t / 9, j = t % 9;
        float s = spa_b[j];
#pragma unroll
        for (int a = 0; a < ATT; a++) s += sh[b][a] * spa_w[j * ATT + a];
        g_spa[t] = 1.f / (1.f + expf(-s));
        float s2 = fld_b[j];
#pragma unroll
        for (int a = 0; a < ATT; a++) s2 += sh[b][a] * fld_w[j * ATT + a];
        sfld[b][j] = 1.f / (1.f + expf(-s2));
    }
    if (tid < BB * KN) {
        int b = tid / KN, n = tid % KN;
        float s = ker_b[n];
#pragma unroll
        for (int a = 0; a < ATT; a++) s += sh[b][a] * ker_w[n * ATT + a];
        sker[b][n] = s;
    }
    __syncthreads();
    if (tid < BB) {
        int b = tid;
        float m = -1e30f;
#pragma unroll
        for (int n = 0; n < KN; n++) m = fmaxf(m, sker[b][n]);
        float e[KN], sum = 0.f;
#pragma unroll
        for (int n = 0; n < KN; n++) { e[n] = expf(sker[b][n] - m); sum += e[n]; }
#pragma unroll
        for (int n = 0; n < KN; n++) sker[b][n] = e[n] / sum;
    }
    __syncthreads();
    for (int t = tid; t < BB * KN * 9; t += 256) {
        int b = t / (KN * 9), n = (t / 9) % KN, j = t % 9;
        g_coef[t] = sker[b][n] * sfld[b][j];
    }
}

// ---------------- kernel 3: aggregation -> bf16 hi/lo filter tiles ---------
// (R8 verbatim) grid (64, 9): blockIdx.y owns ONE pq.
__global__ void __launch_bounds__(256) agg_kernel(const float* __restrict__ weight) {
    __shared__ float scoef[BB * KN * 9];
    __shared__ float sch[BB * CIN];
    __shared__ float sfl[BB * COUT];
    __shared__ float sspa[BB * 9];
    for (int t = threadIdx.x; t < BB * KN * 9; t += 256) scoef[t] = g_coef[t];
    for (int t = threadIdx.x; t < BB * CIN; t += 256) sch[t] = g_ch[t];
    for (int t = threadIdx.x; t < BB * COUT; t += 256) sfl[t] = g_fl[t];
    for (int t = threadIdx.x; t < BB * 9; t += 256) sspa[t] = g_spa[t];
    __syncthreads();
    const int oi = blockIdx.x * 256 + threadIdx.x;   // 0..16383
    const int o = oi >> 7, i = oi & 127;
    const int pq = blockIdx.y;
    const size_t nstride = (size_t)COUT * CIN * 81;
    const float* wbase = weight + (size_t)oi * 81 + pq * 9;
    float w[KN * 9];
#pragma unroll
    for (int n = 0; n < KN; n++)
#pragma unroll
        for (int uv = 0; uv < 9; uv++)
            w[n * 9 + uv] = __ldg(wbase + n * nstride + uv);
#pragma unroll 1
    for (int bg = 0; bg < 4; bg++) {
        const int b0 = bg * 4;
        float acc[4] = {0.f, 0.f, 0.f, 0.f};
#pragma unroll
        for (int k = 0; k < KN * 9; k++) {
            float wv = w[k];
#pragma unroll
            for (int bb = 0; bb < 4; bb++)
                acc[bb] += wv * scoef[(b0 + bb) * (KN * 9) + k];
        }
#pragma unroll
        for (int bb = 0; bb < 4; bb++) {
            int b = b0 + bb;
            float s = acc[bb] * sch[b * CIN + i] * sfl[b * COUT + o] * sspa[b * 9 + pq];
            __nv_bfloat16 h = __float2bfloat16(s);
            __nv_bfloat16 l = __float2bfloat16(s - __bfloat162float(h));
            size_t oidx = (((size_t)b * 9 + pq) * 128 + o) * 128 + i;
            g_ah[oidx] = h;
            g_al[oidx] = l;
        }
    }
}

// ---------------- kernel 4: implicit-GEMM conv on mma.sync (bf16 hi/lo) ----
// R11 conv with TWO changes:
//  (1) A-copy via cp.async.cg (overlaps with B-build, no reg round-trip)
//  (2) MMA phase loads Bh+Bl fragments once per ks; A fragments once per
//      (mt, plane): LDSM count per ks 24 -> 16.
#define APITCH 80   // 32 k * 2B = 64B payload, padded to 80B (conflict-free)

__global__ void __launch_bounds__(256, 2) conv_mma_kernel(float* __restrict__ out) {
    __shared__ __align__(16) char sm[4 * 128 * APITCH];
    const uint32_t sbase = smem_u32(sm);
    const uint32_t sAh = sbase;
    const uint32_t sAl = sbase + 10240u;
    const uint32_t sBh = sbase + 20480u;
    const uint32_t sBl = sbase + 30720u;
    char* smBh = sm + 2 * 128 * APITCH;
    char* smBl = sm + 3 * 128 * APITCH;

    const int tid = threadIdx.x;
    const int wid = tid >> 5;
    const int lid = tid & 31;
    const int b = blockIdx.y;
    const int y0 = blockIdx.x * 2;         // two output rows y0, y0+1

    const int mbase = (wid >> 2) * 64;
    const int nbase = (wid & 3) * 32;

    float acc[4][4][4];
#pragma unroll
    for (int mt = 0; mt < 4; mt++)
#pragma unroll
        for (int nt = 0; nt < 4; nt++)
#pragma unroll
            for (int r = 0; r < 4; r++) acc[mt][nt][r] = 0.f;

    const uint32_t* xsb = g_xs + (size_t)b * CIN * HH * WW;

    // B-build thread mapping
    const int bn = tid & 127;
    const int ihalf = tid >> 7;
    const int brp = bn >> 6;
    const int bpx = bn & 63;

    // A-copy thread mapping
    const int ao = tid >> 1;
    const int au = tid & 1;
    const uint32_t adst_h = sAh + (uint32_t)(ao * APITCH + au * 32);
    const uint32_t adst_l = sAl + (uint32_t)(ao * APITCH + au * 32);

    // ldmatrix lane mapping (validated R8)
    const int r8 = lid & 7;
    const int g1 = (lid >> 3) & 1;
    const int g2 = lid >> 4;
    const uint32_t aoff = (uint32_t)((mbase + g1 * 8 + r8) * APITCH + g2 * 16);
    const uint32_t boff = (uint32_t)((nbase + r8) * APITCH + g1 * 16);

    for (int tap = 0; tap < 9; tap++) {
        const int p = tap / 3 - 1;
        const int q = tap % 3 - 1;
        const int gy = y0 + brp + p;
        const int gx = bpx + q;
        const bool inb = (gx >= 0) && (gx < WW) && (gy >= 0) && (gy < HH);
        const uint32_t* xpix = xsb + (inb ? (gy * WW + gx) : 0);
        const size_t abase = (((size_t)b * 9 + tap) * 128 + ao) * 128;

        for (int kc = 0; kc < 4; kc++) {
            const int ic0 = kc * 32;
            // ---- A copy via cp.async (background during B-build) ----
            {
                const __nv_bfloat16* srcH = g_ah + abase + ic0 + au * 16;
                const __nv_bfloat16* srcL = g_al + abase + ic0 + au * 16;
                cp_async16(adst_h, srcH);
                cp_async16(adst_h + 16, srcH + 8);
                cp_async16(adst_l, srcL);
                cp_async16(adst_l + 16, srcL + 8);
                asm volatile("cp.async.commit_group;" ::: "memory");
            }
            // ---- B build: [n=128][k=32] packed loads + byte_perm split ----
            {
                uint32_t pck[16];
                const uint32_t* src = xpix + (size_t)(ic0 + ihalf * 16) * (HH * WW);
#pragma unroll
                for (int kk = 0; kk < 16; kk++)
                    pck[kk] = inb ? __ldg(src + (size_t)kk * (HH * WW)) : 0u;
                uint32_t h[8], l[8];
#pragma unroll
                for (int j = 0; j < 8; j++) {
                    h[j] = __byte_perm(pck[2 * j], pck[2 * j + 1], 0x7632);
                    l[j] = __byte_perm(pck[2 * j], pck[2 * j + 1], 0x5410);
                }
                char* dh = smBh + bn * APITCH + ihalf * 32;
                char* dl = smBl + bn * APITCH + ihalf * 32;
                *(uint4*)(dh) = *(const uint4*)(h);
                *(uint4*)(dh + 16) = *(const uint4*)(h + 4);
                *(uint4*)(dl) = *(const uint4*)(l);
                *(uint4*)(dl + 16) = *(const uint4*)(l + 4);
            }
            asm volatile("cp.async.wait_group 0;" ::: "memory");
            __syncthreads();

            // ---- MMA: B frags loaded once per ks; A per (mt, plane) ----
#pragma unroll
            for (int ks = 0; ks < 2; ks++) {
                const uint32_t kb = (uint32_t)(ks * 32);
                uint32_t bh[4][2], bl[4][2];
#pragma unroll
                for (int nt = 0; nt < 4; nt++)
                    ldsm_x2(bh[nt], sBh + boff + (uint32_t)(nt * 8 * APITCH) + kb);
#pragma unroll
                for (int nt = 0; nt < 4; nt++)
                    ldsm_x2(bl[nt], sBl + boff + (uint32_t)(nt * 8 * APITCH) + kb);
#pragma unroll
                for (int mt = 0; mt < 4; mt++) {
                    uint32_t ah[4];
                    ldsm_x4(ah, sAh + aoff + (uint32_t)(mt * 16 * APITCH) + kb);
#pragma unroll
                    for (int nt = 0; nt < 4; nt++) mma16816(acc[mt][nt], ah, bh[nt]);
#pragma unroll
                    for (int nt = 0; nt < 4; nt++) mma16816(acc[mt][nt], ah, bl[nt]);
                }
#pragma unroll
                for (int mt = 0; mt < 4; mt++) {
                    uint32_t al[4];
                    ldsm_x4(al, sAl + aoff + (uint32_t)(mt * 16 * APITCH) + kb);
#pragma unroll
                    for (int nt = 0; nt < 4; nt++) mma16816(acc[mt][nt], al, bh[nt]);
                }
            }
            __syncthreads();
        }
    }

    // ---- epilogue: direct stores (fl already folded into agg) ----
    float* ob = out + (size_t)b * COUT * HH * WW;
#pragma unroll
    for (int mt = 0; mt < 4; mt++) {
        const int o = mbase + mt * 16 + (lid >> 2);
#pragma unroll
        for (int nt = 0; nt < 4; nt++) {
            const int nn = nbase + nt * 8 + (lid & 3) * 2;
            const int rp = nn >> 6, px = nn & 63;
            float* dst = ob + ((size_t)o * HH + (y0 + rp)) * WW + px;
            float2 v0 = make_float2(acc[mt][nt][0], acc[mt][nt][1]);
            float2 v1 = make_float2(acc[mt][nt][2], acc[mt][nt][3]);
            *(float2*)(dst) = v0;
            *(float2*)(dst + 8 * (size_t)HH * WW) = v1;
        }
    }
}

// ---------------- launch ----------------------------------------------------
extern "C" void kernel_launch(void* const* d_in, const int* in_sizes, int n_in,
                              void* d_out, int out_size) {
    const float* x        = (const float*)d_in[0];
    const float* weight   = (const float*)d_in[1];
    const float* fc_w     = (const float*)d_in[2];
    const float* bn_gamma = (const float*)d_in[3];
    const float* bn_beta  = (const float*)d_in[4];
    const float* bn_mean  = (const float*)d_in[5];
    const float* bn_var   = (const float*)d_in[6];
    const float* ch_w     = (const float*)d_in[7];
    const float* ch_b     = (const float*)d_in[8];
    const float* flt_w    = (const float*)d_in[9];
    const float* flt_b    = (const float*)d_in[10];
    const float* spa_w    = (const float*)d_in[11];
    const float* spa_b    = (const float*)d_in[12];
    const float* fld_w    = (const float*)d_in[13];
    const float* fld_b    = (const float*)d_in[14];
    const float* ker_w    = (const float*)d_in[15];
    const float* ker_b    = (const float*)d_in[16];
    float* out = (float*)d_out;

    xsplit_pool_kernel<<<BB * CIN, 256>>>(x);
    attn_kernel<<<1, 256>>>(fc_w, bn_gamma, bn_beta, bn_mean, bn_var,
                            ch_w, ch_b, flt_w, flt_b, spa_w, spa_b,
                            fld_w, fld_b, ker_w, ker_b);
    agg_kernel<<<dim3(64, 9), 256>>>(weight);
    conv_mma_kernel<<<dim3(32, BB), 256>>>(out);
}